// round 14
// baseline (speedup 1.0000x reference)
#include <cuda_runtime.h>
#include <cuda_fp16.h>
#include <cstdint>

// Problem constants
#define B_WIN 256
#define NTOK  144
#define DIM   384
#define HEADS 12
#define HD    32
#define QKV_N 1152
#define MROWS (B_WIN*NTOK)        // 36864
#define QSCALE 0.17677669529663689f   // 32^-0.5
#define LOG2E  1.4426950408889634f
#define QSCL2E (QSCALE * LOG2E)

// Packed planes inside g_qkvp (all single fp16, 64B rows, 4 chunks,
// swizzle phys = c ^ ((r>>1)&3)):
#define Q_OFF 0ll
#define K_OFF 28311552ll
#define V_OFF 56623104ll

// ---------------- Scratch (static device globals; allocation-free) ----------
__device__ char   g_qkvp[84934656];
__device__ __half g_xa[14155776];      // x fp16, [36864][384]
__device__ __half g_wqkvT[442368];     // [1152][384]
__device__ __half g_woutT[147456];     // [384][384]
__device__ __half g_att[14155776];     // attention out fp16, [36864][384]
__device__ float  g_maskl[165888];     // mask * log2e, [8][144][144]

// ---------------- helpers ---------------------------------------------------
__device__ __forceinline__ uint32_t smem_u32(const void* p) {
    return (uint32_t)__cvta_generic_to_shared(p);
}
__device__ __forceinline__ uint32_t packf2(float x, float y) {
    __half2 h = __float22half2_rn(make_float2(x, y));
    return *(uint32_t*)&h;
}
__device__ __forceinline__ float ex2(float x) {
    float y;
    asm("ex2.approx.ftz.f32 %0, %1;" : "=f"(y) : "f"(x));
    return y;
}
__device__ __forceinline__ void ldsm_x4(uint32_t* r, uint32_t addr) {
    asm volatile("ldmatrix.sync.aligned.m8n8.x4.shared.b16 {%0,%1,%2,%3}, [%4];"
                 : "=r"(r[0]), "=r"(r[1]), "=r"(r[2]), "=r"(r[3]) : "r"(addr));
}
__device__ __forceinline__ void ldsm_x4_t(uint32_t* r, uint32_t addr) {
    asm volatile("ldmatrix.sync.aligned.m8n8.x4.trans.shared.b16 {%0,%1,%2,%3}, [%4];"
                 : "=r"(r[0]), "=r"(r[1]), "=r"(r[2]), "=r"(r[3]) : "r"(addr));
}
__device__ __forceinline__ void mma_f16(float* c, const uint32_t* a, const uint32_t* b) {
    asm volatile(
        "mma.sync.aligned.m16n8k16.row.col.f32.f16.f16.f32 "
        "{%0,%1,%2,%3}, {%4,%5,%6,%7}, {%8,%9}, {%0,%1,%2,%3};"
        : "+f"(c[0]), "+f"(c[1]), "+f"(c[2]), "+f"(c[3])
        : "r"(a[0]), "r"(a[1]), "r"(a[2]), "r"(a[3]), "r"(b[0]), "r"(b[1]));
}
__device__ __forceinline__ void cp_async16(uint32_t s, const void* g) {
    asm volatile("cp.async.cg.shared.global [%0], [%1], 16;" :: "r"(s), "l"(g));
}
#define CP_COMMIT() asm volatile("cp.async.commit_group;" ::: "memory")
#define CP_WAIT1()  asm volatile("cp.async.wait_group 1;" ::: "memory")
#define CP_WAIT0()  asm volatile("cp.async.wait_group 0;" ::: "memory")

// ---------------------------------------------------------------------------
// Fused prep: x fp32->fp16, w transposes, mask*log2e
// ---------------------------------------------------------------------------
__global__ void prep_kernel(const float* __restrict__ x,
                            const float* __restrict__ w_qkv,
                            const float* __restrict__ w_out,
                            const float* __restrict__ mask,
                            __half* __restrict__ xa,
                            __half* __restrict__ wqT,
                            __half* __restrict__ woT,
                            float* __restrict__ maskl)
{
    const int tid0 = blockIdx.x * blockDim.x + threadIdx.x;
    const int stride = gridDim.x * blockDim.x;
    for (int idx = tid0; idx < MROWS * DIM / 4; idx += stride) {
        float4 v = ((const float4*)x)[idx];
        ((uint2*)xa)[idx] = make_uint2(packf2(v.x, v.y), packf2(v.z, v.w));
    }
    for (int idx = tid0; idx < DIM * QKV_N; idx += stride) {
        int n = idx / DIM, k = idx - n * DIM;
        wqT[idx] = __float2half_rn(w_qkv[(size_t)k * QKV_N + n]);
    }
    for (int idx = tid0; idx < DIM * DIM; idx += stride) {
        int n = idx / DIM, k = idx - n * DIM;
        woT[idx] = __float2half_rn(w_out[(size_t)k * DIM + n]);
    }
    for (int idx = tid0; idx < 8 * NTOK * NTOK; idx += stride)
        maskl[idx] = mask[idx] * LOG2E;
}

// ---------------------------------------------------------------------------
// HMMA fp16 GEMM, BK=32, 3-stage cp.async, 2 CTAs/SM. (unchanged from R13)
// ---------------------------------------------------------------------------
#define TB32 8192
#define STG32 (2 * TB32)
#define NKC 12

__global__ __launch_bounds__(256, 2)
void hmma_gemm_kernel(const __half* __restrict__ Aa,
                      const __half* __restrict__ Bs,
                      const float* __restrict__ bias,
                      float* __restrict__ outp, int mode)
{
    extern __shared__ char smem[];
    const uint32_t usm = smem_u32(smem);

    const int tid = threadIdx.x;
    const int wid = tid >> 5, lane = tid & 31;
    const int bm = blockIdx.y * 128;
    const int bn = blockIdx.x * 128;
    const int wm = wid >> 2, wn = wid & 3;
    const int m0w = wm * 64, n0w = wn * 32;

    const int r0l = tid >> 2;
    const int c0l = tid & 3;

    float acc[4][4][4];
#pragma unroll
    for (int mt = 0; mt < 4; mt++)
#pragma unroll
        for (int nt = 0; nt < 4; nt++)
#pragma unroll
            for (int e = 0; e < 4; e++) acc[mt][nt][e] = 0.f;

    const int lr = lane & 15;
    const int lc = lane >> 4;

#define LOAD_STAGE32(kc, buf)                                                   \
    {                                                                           \
        uint32_t s0 = usm + (buf) * STG32;                                      \
        _Pragma("unroll")                                                       \
        for (int it = 0; it < 2; it++) {                                        \
            int r = r0l + it * 64;                                              \
            size_t gA = (size_t)(bm + r) * 384 + (kc) * 32 + c0l * 8;           \
            size_t gB = (size_t)(bn + r) * 384 + (kc) * 32 + c0l * 8;           \
            uint32_t d = r * 64 + ((c0l ^ ((r >> 1) & 3)) * 16);                \
            cp_async16(s0 + d, Aa + gA);                                        \
            cp_async16(s0 + TB32 + d, Bs + gB);                                 \
        }                                                                       \
        CP_COMMIT();                                                            \
    }

    LOAD_STAGE32(0, 0);
    LOAD_STAGE32(1, 1);

    int buf = 0;
    for (int kc = 0; kc < NKC; kc++) {
        if (kc < NKC - 1) { CP_WAIT1(); } else { CP_WAIT0(); }
        __syncthreads();
        if (kc + 2 < NKC) {
            int nb = buf + 2; if (nb >= 3) nb -= 3;
            LOAD_STAGE32(kc + 2, nb);
        }

        const uint32_t uA = usm + buf * STG32;
        const uint32_t uB = uA + TB32;

#pragma unroll
        for (int k16 = 0; k16 < 2; k16++) {
            const int chunk = k16 * 2 + lc;
            uint32_t aF[4][4];
            uint32_t bF[4][2];
#pragma unroll
            for (int mt = 0; mt < 4; mt++) {
                int r = m0w + mt * 16 + lr;
                uint32_t off = r * 64 + ((chunk ^ ((r >> 1) & 3)) * 16);
                ldsm_x4(aF[mt], uA + off);
            }
#pragma unroll
            for (int np = 0; np < 2; np++) {
                int r = n0w + np * 16 + lr;
                uint32_t off = r * 64 + ((chunk ^ ((r >> 1) & 3)) * 16);
                uint32_t t[4];
                ldsm_x4(t, uB + off);
                bF[2 * np][0] = t[0]; bF[2 * np][1] = t[2];
                bF[2 * np + 1][0] = t[1]; bF[2 * np + 1][1] = t[3];
            }
#pragma unroll
            for (int mt = 0; mt < 4; mt++)
#pragma unroll
                for (int nt = 0; nt < 4; nt++)
                    mma_f16(acc[mt][nt], aF[mt], bF[nt]);
        }
        __syncthreads();
        if (++buf == 3) buf = 0;
    }
#undef LOAD_STAGE32

    if (mode == 0) {
#pragma unroll
        for (int mt = 0; mt < 4; mt++) {
#pragma unroll
            for (int nt = 0; nt < 4; nt++) {
                int col = bn + n0w + nt * 8 + (lane & 3) * 2;
                int s = col / 384;
                int rem = col - s * 384;
                int hh = rem >> 5, d = rem & 31;
                float sc = (s == 0) ? QSCL2E : 1.0f;
                float b0 = bias[col], b1 = bias[col + 1];
                char* plane = g_qkvp + ((s == 0) ? Q_OFF : (s == 1) ? K_OFF : V_OFF);
                int ch = d >> 3;
                int byt = (d & 7) * 2;
#pragma unroll
                for (int half2_ = 0; half2_ < 2; half2_++) {
                    int row = bm + m0w + mt * 16 + (lane >> 2) + half2_ * 8;
                    int b = row / 144, i = row - b * 144;
                    float v0 = (acc[mt][nt][half2_ * 2 + 0] + b0) * sc;
                    float v1 = (acc[mt][nt][half2_ * 2 + 1] + b1) * sc;
                    char* base = plane + ((size_t)(b * 12 + hh) * 144 + i) * 64;
                    *(uint32_t*)(base + ((ch ^ ((i >> 1) & 3)) * 16) + byt) =
                        packf2(v0, v1);
                }
            }
        }
    } else {
#pragma unroll
        for (int mt = 0; mt < 4; mt++) {
#pragma unroll
            for (int nt = 0; nt < 4; nt++) {
                int col = bn + n0w + nt * 8 + (lane & 3) * 2;
                float b0 = bias[col], b1 = bias[col + 1];
#pragma unroll
                for (int half2_ = 0; half2_ < 2; half2_++) {
                    int row = bm + m0w + mt * 16 + (lane >> 2) + half2_ * 8;
                    float2 v;
                    v.x = acc[mt][nt][half2_ * 2 + 0] + b0;
                    v.y = acc[mt][nt][half2_ * 2 + 1] + b1;
                    *(float2*)(outp + (size_t)row * 384 + col) = v;
                }
            }
        }
    }
}

// ---------------------------------------------------------------------------
// Flash-style HMMA attention, split-j: 576 threads, 18 warps.
// Warp pair (p, p+9) shares m-tile p; half 0 owns j 0..63 (n-tiles 0..7,
// PV kk 0..3), half 1 owns j 64..143 (n-tiles 8..17, PV kk 4..8).
// Cross-warp: row-sum exchange (ssum) + PV partial-O reduction (so).
// ---------------------------------------------------------------------------
__global__ __launch_bounds__(576, 1)
void attn_mma_kernel(const float* __restrict__ bias_table,
                     const int*   __restrict__ pos_idx)
{
    extern __shared__ char sm[];
    char*  sQ   = sm;                       // 9216
    char*  sK   = sm + 9216;                // 9216
    char*  sV   = sm + 18432;               // 9216
    float* sB   = (float*)(sm + 27648);     // 2592 f
    float* ssum = (float*)(sm + 38016);     // 288 f
    float* so   = (float*)(sm + 39168);     // 4608 f (18432 B)
    const uint32_t uQ = smem_u32(sQ), uK = smem_u32(sK), uV = smem_u32(sV);

    const int bh = blockIdx.x;
    const int b = bh / HEADS, h = bh - b * HEADS;
    const int g  = b >> 5;
    const int t  = b & 31;
    const int mw = b & 7;

    const int tid = threadIdx.x;
    const int wid = tid >> 5, lane = tid & 31;
    const int p    = wid % 9;          // m-tile
    const int half = wid / 9;          // j-half

    // 1. QKV tile copy via cp.async (one line per thread per tensor)
    {
        const char* q = g_qkvp + Q_OFF + (size_t)bh * 9216;
        const char* k = g_qkvp + K_OFF + (size_t)bh * 9216;
        const char* v = g_qkvp + V_OFF + (size_t)bh * 9216;
        cp_async16(uQ + tid * 16, q + tid * 16);
        cp_async16(uK + tid * 16, k + tid * 16);
        cp_async16(uV + tid * 16, v + tid * 16);
        CP_COMMIT();
    }

    // 2. bias gather into registers (x log2e)
    float bvr[5];
#pragma unroll
    for (int kq = 0; kq < 5; kq++) {
        int s = tid + kq * 576;
        if (s < 2592)
            bvr[kq] = bias_table[(size_t)pos_idx[8 * s + g] * (32 * HEADS)
                                 + t * HEADS + h] * LOG2E;
    }

    CP_WAIT0();
    __syncthreads();

    const int m0 = p * 16;
    const int gr = lane >> 2, q2 = lane & 3;
    const int i0 = m0 + gr, i1 = i0 + 8;

    const int NTL = half ? 10 : 8;       // local n-tiles
    const int nb  = half ? 8 : 0;        // n-tile base
    const int npb = half ? 4 : 0;        // ldsm pair base
    const int npc = half ? 5 : 4;        // ldsm pairs
    const int kb  = half ? 4 : 0;        // PV kk base
    const int kc_ = half ? 5 : 4;        // PV kk count

    // 3. QK^T over this warp's j-range
    float c[10][4];
#pragma unroll
    for (int nt = 0; nt < 10; nt++)
#pragma unroll
        for (int e = 0; e < 4; e++) c[nt][e] = 0.f;

    const int lr = lane & 15, lc = lane >> 4;
#pragma unroll
    for (int kk = 0; kk < 2; kk++) {
        uint32_t aF[4];
        {
            int r = m0 + lr;
            int ch = kk * 2 + lc;
            ldsm_x4(aF, uQ + r * 64 + ((ch ^ ((r >> 1) & 3)) * 16));
        }
#pragma unroll
        for (int npl = 0; npl < 5; npl++) {
            if (npl >= npc) break;
            int np = npb + npl;
            int r = np * 16 + lr;
            int ch = kk * 2 + lc;
            uint32_t tK[4];
            ldsm_x4(tK, uK + r * 64 + ((ch ^ ((r >> 1) & 3)) * 16));
            uint32_t b0[2] = {tK[0], tK[2]}, b1[2] = {tK[1], tK[3]};
            mma_f16(c[2 * npl],     aF, b0);
            mma_f16(c[2 * npl + 1], aF, b1);
        }
    }

    // 4. publish gathered bias
#pragma unroll
    for (int kq = 0; kq < 5; kq++) {
        int s = tid + kq * 576;
        if (s < 2592) sB[s] = bvr[kq];
    }
    __syncthreads();

    // 5. partial softmax: e = 2^(c + mask + bias) over this j-range
    float s0 = 0.f, s1 = 0.f;
    {
        const float* mrow0 = g_maskl + ((size_t)mw * 144 + i0) * 144;
        const float* mrow1 = g_maskl + ((size_t)mw * 144 + i1) * 144;
        const float* brow0 = sB + (i0 % 18) * 144;
        const float* brow1 = sB + (i1 % 18) * 144;
#pragma unroll
        for (int ntl = 0; ntl < 10; ntl++) {
            if (ntl >= NTL) break;
            int j = (nb + ntl) * 8 + q2 * 2;
            float2 mv0 = *(const float2*)(mrow0 + j);
            float2 mv1 = *(const float2*)(mrow1 + j);
            float2 bv0 = *(const float2*)(brow0 + j);
            float2 bv1 = *(const float2*)(brow1 + j);
            c[ntl][0] = ex2(c[ntl][0] + mv0.x + bv0.x); s0 += c[ntl][0];
            c[ntl][1] = ex2(c[ntl][1] + mv0.y + bv0.y); s0 += c[ntl][1];
            c[ntl][2] = ex2(c[ntl][2] + mv1.x + bv1.x); s1 += c[ntl][2];
            c[ntl][3] = ex2(c[ntl][3] + mv1.y + bv1.y); s1 += c[ntl][3];
        }
    }
    s0 += __shfl_xor_sync(0xffffffffu, s0, 1);
    s0 += __shfl_xor_sync(0xffffffffu, s0, 2);
    s1 += __shfl_xor_sync(0xffffffffu, s1, 1);
    s1 += __shfl_xor_sync(0xffffffffu, s1, 2);
    if (q2 == 0) {
        ssum[half * 144 + i0] = s0;
        ssum[half * 144 + i1] = s1;
    }
    __syncthreads();
    float inv0 = 1.f / (ssum[i0] + ssum[144 + i0]);
    float inv1 = 1.f / (ssum[i1] + ssum[144 + i1]);

    // 6. P -> packed fp16 A-frags for this warp's kk range
    uint32_t ph[20];
#pragma unroll
    for (int kkl = 0; kkl < 5; kkl++) {
        if (kkl >= kc_) break;
#pragma unroll
        for (int pp = 0; pp < 4; pp++) {
            int ntl = (pp < 2) ? 2 * kkl : 2 * kkl + 1;
            float sc0 = (pp & 1) ? inv1 : inv0;
            ph[kkl * 4 + pp] = packf2(c[ntl][(pp & 1) * 2 + 0] * sc0,
                                      c[ntl][(pp & 1) * 2 + 1] * sc0);
        }
    }

    // 7. PV over this warp's kk range (partial O)
    float o[4][4];
#pragma unroll
    for (int ng = 0; ng < 4; ng++)
#pragma unroll
        for (int e = 0; e < 4; e++) o[ng][e] = 0.f;

    const int grp = lane >> 3, wi = lane & 7;
#pragma unroll
    for (int kkl = 0; kkl < 5; kkl++) {
        if (kkl >= kc_) break;
        int kk = kb + kkl;
        int r = kk * 16 + (grp & 1) * 8 + wi;
#pragma unroll
        for (int ncp = 0; ncp < 2; ncp++) {
            int ch = ncp * 2 + (grp >> 1);
            uint32_t tv[4];
            ldsm_x4_t(tv, uV + r * 64 + ((ch ^ ((r >> 1) & 3)) * 16));
            uint32_t b0[2] = {tv[0], tv[1]}, b1[2] = {tv[2], tv[3]};
            mma_f16(o[ncp * 2],     ph + kkl * 4, b0);
            mma_f16(o[ncp * 2 + 1], ph + kkl * 4, b1);
        }
    }

    // 8. cross-half O reduction: half 1 stores, half 0 adds + writes gmem
    if (half == 1) {
        float* dst = so + (p * 32 + lane) * 16;
#pragma unroll
        for (int ng = 0; ng < 4; ng++)
            *(float4*)(dst + ng * 4) = make_float4(o[ng][0], o[ng][1],
                                                   o[ng][2], o[ng][3]);
    }
    __syncthreads();
    if (half == 0) {
        const float* src = so + (p * 32 + lane) * 16;
#pragma unroll
        for (int ng = 0; ng < 4; ng++) {
            float4 v = *(const float4*)(src + ng * 4);
            o[ng][0] += v.x; o[ng][1] += v.y; o[ng][2] += v.z; o[ng][3] += v.w;
        }
#pragma unroll
        for (int ng = 0; ng < 4; ng++) {
            int d = ng * 8 + q2 * 2;
            int col = h * 32 + d;
            size_t r0o = ((size_t)b * 144 + i0) * 384 + col;
            size_t r1o = ((size_t)b * 144 + i1) * 384 + col;
            *(uint32_t*)(g_att + r0o) = packf2(o[ng][0], o[ng][1]);
            *(uint32_t*)(g_att + r1o) = packf2(o[ng][2], o[ng][3]);
        }
    }
}

// ---------------------------------------------------------------------------
extern "C" void kernel_launch(void* const* d_in, const int* in_sizes, int n_in,
                              void* d_out, int out_size)
{
    const float* x          = (const float*)d_in[0];
    const float* mask       = (const float*)d_in[1];
    const float* w_qkv      = (const float*)d_in[2];
    const float* b_qkv      = (const float*)d_in[3];
    const float* w_out      = (const float*)d_in[4];
    const float* b_out      = (const float*)d_in[5];
    const float* bias_table = (const float*)d_in[6];
    const int*   pos_idx    = (const int*)d_in[7];
    float* out = (float*)d_out;

    __half *xa, *wqT, *woT, *att;
    float* maskl;
    cudaGetSymbolAddress((void**)&xa, g_xa);
    cudaGetSymbolAddress((void**)&wqT, g_wqkvT);
    cudaGetSymbolAddress((void**)&woT, g_woutT);
    cudaGetSymbolAddress((void**)&att, g_att);
    cudaGetSymbolAddress((void**)&maskl, g_maskl);

    const int smem_gemm = 3 * STG32;  // 48 KB
    cudaFuncSetAttribute(hmma_gemm_kernel, cudaFuncAttributeMaxDynamicSharedMemorySize,
                         smem_gemm);
    const int smem_attn = 39168 + 18432;  // 57600
    cudaFuncSetAttribute(attn_mma_kernel, cudaFuncAttributeMaxDynamicSharedMemorySize,
                         smem_attn);

    prep_kernel<<<1024, 256>>>(x, w_qkv, w_out, mask, xa, wqT, woT, maskl);
    // qkv projection -> packed q/k/v
    hmma_gemm_kernel<<<dim3(QKV_N / 128, MROWS / 128), 256, smem_gemm>>>(
        xa, wqT, b_qkv, nullptr, 0);
    // attention
    attn_mma_kernel<<<B_WIN * HEADS, 576, smem_attn>>>(bias_table, pos_idx);
    // output projection
    hmma_gemm_kernel<<<dim3(DIM / 128, MROWS / 128), 256, smem_gemm>>>(
        att, woT, b_out, out, 1);
}